// round 9
// baseline (speedup 1.0000x reference)
#include <cuda_runtime.h>
#include <cstdint>

#define CZ  128
#define HD  64
#define P   64      // pixels per CTA
#define NT  256
#define NW  8
#define XST 132     // [row][k] stride: scalar LDS banks 4*gid+tig -> conflict-free

static __device__ __forceinline__ float tf32r(float x) {
    float y; asm("cvt.rna.tf32.f32 %0, %1;" : "=f"(y) : "f"(x)); return y;
}

static __device__ __forceinline__ void mma8(float* d,
    float a0, float a1, float a2, float a3, float b0, float b1)
{
    asm volatile("mma.sync.aligned.m16n8k8.row.col.f32.tf32.tf32.f32 "
        "{%0,%1,%2,%3}, {%4,%5,%6,%7}, {%8,%9}, {%0,%1,%2,%3};"
        : "+f"(d[0]), "+f"(d[1]), "+f"(d[2]), "+f"(d[3])
        : "r"(__float_as_uint(a0)), "r"(__float_as_uint(a1)),
          "r"(__float_as_uint(a2)), "r"(__float_as_uint(a3)),
          "r"(__float_as_uint(b0)), "r"(__float_as_uint(b1)));
}

// Warp computes 32 rows (mt) x 32 cols (nq); K = 8*KT.
static __device__ __forceinline__ void gemm32(
    float acc[2][4][4], const float* A, int ast, const float* wt,
    int mt, int nq, int gid, int tig, int KT)
{
    const float* ar0 = A + (mt * 32 + gid) * ast + tig;
    const float* ar1 = ar0 + 8 * ast;
    const float* ar2 = ar0 + 16 * ast;
    const float* ar3 = ar0 + 24 * ast;
    const float* bp  = wt + (nq * 32 + gid) * XST + tig;
    #pragma unroll 4
    for (int kt = 0; kt < KT; kt++) {
        const int k0 = kt * 8;
        float a00 = ar0[k0], a01 = ar1[k0], a02 = ar0[k0 + 4], a03 = ar1[k0 + 4];
        float a10 = ar2[k0], a11 = ar3[k0], a12 = ar2[k0 + 4], a13 = ar3[k0 + 4];
        #pragma unroll
        for (int nt = 0; nt < 4; nt++) {
            float b0 = bp[nt * 8 * XST + k0];
            float b1 = bp[nt * 8 * XST + k0 + 4];
            mma8(acc[0][nt], a00, a01, a02, a03, b0, b1);
            mma8(acc[1][nt], a10, a11, a12, a13, b0, b1);
        }
    }
}

// LayerNorm 64 rows x 128 cols -> tf32 into [row][k] stride XST.
static __device__ __forceinline__ void ln64(
    const float* __restrict__ src, long base, int R, float* dst,
    float4 g4, float4 b4, int wid, int lane)
{
    const int c4 = lane * 4;
    #pragma unroll
    for (int r = wid; r < P; r += NW) {
        long row = base + r;
        float4 x = make_float4(0.f, 0.f, 0.f, 0.f);
        if (row < R) x = *(const float4*)(src + row * (long)CZ + c4);
        float s = x.x + x.y + x.z + x.w;
        float q = fmaf(x.x, x.x, fmaf(x.y, x.y, fmaf(x.z, x.z, x.w * x.w)));
        #pragma unroll
        for (int o = 16; o; o >>= 1) {
            s += __shfl_xor_sync(0xffffffffu, s, o);
            q += __shfl_xor_sync(0xffffffffu, q, o);
        }
        float m  = s * (1.f / CZ);
        float v  = fmaxf(q * (1.f / CZ) - m * m, 0.f);
        float ri = rsqrtf(v + 1e-5f);
        float* xr = dst + r * XST + c4;
        xr[0] = tf32r((x.x - m) * ri * g4.x + b4.x);
        xr[1] = tf32r((x.y - m) * ri * g4.y + b4.y);
        xr[2] = tf32r((x.z - m) * ri * g4.z + b4.z);
        xr[3] = tf32r((x.w - m) * ri * g4.w + b4.w);
    }
}

// Stage two k-major [128][64] weights into wt[n][k] (n<64: W1, else W2).
static __device__ __forceinline__ void stageW2(
    float* wt, const float* __restrict__ W1, const float* __restrict__ W2, int tid)
{
    #pragma unroll 1
    for (int i = tid; i < 4096; i += NT) {
        const int m  = i >> 11;
        const int k  = (i >> 4) & 127;
        const int ng = i & 15;
        const float* Ws = m ? W2 : W1;
        float4 w = *(const float4*)(Ws + k * HD + ng * 4);
        const int n = m * 64 + ng * 4;
        wt[(n + 0) * XST + k] = tf32r(w.x);
        wt[(n + 1) * XST + k] = tf32r(w.y);
        wt[(n + 2) * XST + k] = tf32r(w.z);
        wt[(n + 3) * XST + k] = tf32r(w.w);
    }
}

__global__ void __launch_bounds__(NT, 2)
tpa_mma7(const float* __restrict__ tmpl, const float* __restrict__ pair,
         const float* __restrict__ lpg, const float* __restrict__ lpb,
         const float* __restrict__ ltg, const float* __restrict__ ltb,
         const float* __restrict__ Wq,  const float* __restrict__ Wk,
         const float* __restrict__ Wv,  const float* __restrict__ Wg,
         const float* __restrict__ bg,  const float* __restrict__ Wo,
         const float* __restrict__ bo,  float* __restrict__ out,
         int R, int T)
{
    extern __shared__ float smf[];
    float* xs  = smf;                 // 64 x XST : LN'd activations (single buffer; vals later)
    float* wt  = xs + P * XST;        // 128 x XST: weights [n][k]
    float* rs  = wt + 128 * XST;      // 256 : softmax rescale   (p*4+h)
    float* ws  = rs + 256;            // 256 : softmax new weight
    float* ls  = ws + 256;            // 256 : 1/l
    float* bgs = ls + 256;            // 64
    float* bos = bgs + HD;            // 128

    const int tid  = threadIdx.x;
    const int lane = tid & 31;
    const int wid  = tid >> 5;
    const int mt   = wid & 1;         // m-tile (32 rows)
    const int nq   = wid >> 1;        // n quarter (32 cols)
    const int gid  = lane >> 2;
    const int tig  = lane & 3;
    const bool isK = (nq < 2);
    const long base = (long)blockIdx.x * P;

    if (tid < HD)  bgs[tid] = bg[tid];
    else if (tid >= 64 && tid < 64 + CZ) bos[tid - 64] = bo[tid - 64];

    const int c4 = lane * 4;
    const float4 gp = *(const float4*)(lpg + c4), bp = *(const float4*)(lpb + c4);
    const float4 gt = *(const float4*)(ltg + c4), bt = *(const float4*)(ltb + c4);

    // ---------------- Phase A: LN(pair)->xs, Wq|Wg, QG GEMM ----------------
    ln64(pair, base, R, xs, gp, bp, wid, lane);
    stageW2(wt, Wq, Wg, tid);
    __syncthreads();

    float qf[2][4][4] = {};           // K-warps: Q fragments; V-warps: G after sigmoid
    gemm32(qf, xs, XST, wt, mt, nq, gid, tig, 16);
    if (!isK) {                       // sigmoid in place -> qf holds G
        #pragma unroll
        for (int f = 0; f < 2; f++)
            #pragma unroll
            for (int nt = 0; nt < 4; nt++) {
                const int c = (nq - 2) * 32 + nt * 8 + tig * 2;
                qf[f][nt][0] = 1.f / (1.f + __expf(-(qf[f][nt][0] + bgs[c])));
                qf[f][nt][1] = 1.f / (1.f + __expf(-(qf[f][nt][1] + bgs[c + 1])));
                qf[f][nt][2] = 1.f / (1.f + __expf(-(qf[f][nt][2] + bgs[c])));
                qf[f][nt][3] = 1.f / (1.f + __expf(-(qf[f][nt][3] + bgs[c + 1])));
            }
    }
    __syncthreads();                  // QG read of xs/wt complete

    stageW2(wt, Wk, Wv, tid);
    ln64(tmpl, base, R, xs, gt, bt, wid, lane);     // LN(t=0)

    float m8[8], l8[8];               // K-warp softmax state (tig==0 authoritative)
    #pragma unroll
    for (int i = 0; i < 8; i++) { m8[i] = __int_as_float(0xff800000); l8[i] = 0.f; }
    float vAcc[2][4][4] = {};
    __syncthreads();

    // ---------------- template loop: 2 syncs per t ----------------
    #pragma unroll 1
    for (int t = 0; t < T; t++) {
        float kv[2][4][4] = {};
        gemm32(kv, xs, XST, wt, mt, nq, gid, tig, 16);

        if (isK) {                    // in-fragment scores + online softmax
            float sc[2][2][2];        // [f][rowhalf][headhalf]
            #pragma unroll
            for (int f = 0; f < 2; f++)
                #pragma unroll
                for (int hh = 0; hh < 2; hh++) {
                    const int nt0 = hh * 2;
                    #pragma unroll
                    for (int rh = 0; rh < 2; rh++) {
                        const int j = rh * 2;
                        float s = qf[f][nt0][j] * kv[f][nt0][j];
                        s = fmaf(qf[f][nt0][j + 1],     kv[f][nt0][j + 1],     s);
                        s = fmaf(qf[f][nt0 + 1][j],     kv[f][nt0 + 1][j],     s);
                        s = fmaf(qf[f][nt0 + 1][j + 1], kv[f][nt0 + 1][j + 1], s);
                        sc[f][rh][hh] = s;
                    }
                }
            #pragma unroll
            for (int f = 0; f < 2; f++)
                #pragma unroll
                for (int rh = 0; rh < 2; rh++)
                    #pragma unroll
                    for (int hh = 0; hh < 2; hh++) {
                        float v = sc[f][rh][hh];
                        v += __shfl_xor_sync(0xffffffffu, v, 1);
                        v += __shfl_xor_sync(0xffffffffu, v, 2);
                        sc[f][rh][hh] = v;
                    }
            if (tig == 0) {
                #pragma unroll
                for (int f = 0; f < 2; f++)
                    #pragma unroll
                    for (int rh = 0; rh < 2; rh++)
                        #pragma unroll
                        for (int hh = 0; hh < 2; hh++) {
                            const int i = f * 4 + rh * 2 + hh;
                            float sd = sc[f][rh][hh] * 0.25f;   // 1/sqrt(D=16)
                            float mn = fmaxf(m8[i], sd);
                            float rr = __expf(m8[i] - mn);
                            float ww = __expf(sd - mn);
                            l8[i] = l8[i] * rr + ww;
                            m8[i] = mn;
                            const int r = mt * 32 + f * 16 + rh * 8 + gid;
                            const int h = nq * 2 + hh;
                            rs[r * 4 + h] = rr;
                            ws[r * 4 + h] = ww;
                        }
            }
        }
        __syncthreads();              // S1: rs/ws ready; xs fully read by GEMM

        if (!isK) {                   // V online accumulate from fragments
            #pragma unroll
            for (int f = 0; f < 2; f++) {
                const int r0 = mt * 32 + f * 16 + gid, r1 = r0 + 8;
                #pragma unroll
                for (int nt = 0; nt < 4; nt++) {
                    const int h = ((nq - 2) * 32 + nt * 8) >> 4;
                    float rr0 = rs[r0 * 4 + h], ww0 = ws[r0 * 4 + h];
                    float rr1 = rs[r1 * 4 + h], ww1 = ws[r1 * 4 + h];
                    vAcc[f][nt][0] = fmaf(vAcc[f][nt][0], rr0, ww0 * kv[f][nt][0]);
                    vAcc[f][nt][1] = fmaf(vAcc[f][nt][1], rr0, ww0 * kv[f][nt][1]);
                    vAcc[f][nt][2] = fmaf(vAcc[f][nt][2], rr1, ww1 * kv[f][nt][2]);
                    vAcc[f][nt][3] = fmaf(vAcc[f][nt][3], rr1, ww1 * kv[f][nt][3]);
                }
            }
        }
        if (t + 1 < T)                // LN(t+1) overwrites xs (read done pre-S1)
            ln64(tmpl + (long)(t + 1) * R * CZ, base, R, xs, gt, bt, wid, lane);
        if (t == T - 1) {             // last trip: publish 1/l (Wo staged after loop)
            if (isK && tig == 0) {
                #pragma unroll
                for (int f = 0; f < 2; f++)
                    #pragma unroll
                    for (int rh = 0; rh < 2; rh++)
                        #pragma unroll
                        for (int hh = 0; hh < 2; hh++) {
                            const int i = f * 4 + rh * 2 + hh;
                            const int r = mt * 32 + f * 16 + rh * 8 + gid;
                            ls[r * 4 + nq * 2 + hh] = 1.f / l8[i];
                        }
            }
        }
        __syncthreads();              // S2: xs(t+1)/ls ready; rs/ws consumed
    }

    // ---------------- Phase C: vals -> xs, Wo -> wt, O GEMM ----------------
    if (!isK) {                       // vals = vAcc * G * linv  (G lives in qf)
        #pragma unroll
        for (int f = 0; f < 2; f++) {
            const int r0 = mt * 32 + f * 16 + gid, r1 = r0 + 8;
            #pragma unroll
            for (int nt = 0; nt < 4; nt++) {
                const int c = (nq - 2) * 32 + nt * 8 + tig * 2;
                const int h = ((nq - 2) * 32 + nt * 8) >> 4;
                float li0 = ls[r0 * 4 + h], li1 = ls[r1 * 4 + h];
                xs[r0 * XST + c]     = tf32r(vAcc[f][nt][0] * qf[f][nt][0] * li0);
                xs[r0 * XST + c + 1] = tf32r(vAcc[f][nt][1] * qf[f][nt][1] * li0);
                xs[r1 * XST + c]     = tf32r(vAcc[f][nt][2] * qf[f][nt][2] * li1);
                xs[r1 * XST + c + 1] = tf32r(vAcc[f][nt][3] * qf[f][nt][3] * li1);
            }
        }
    }
    {   // stage Wo[k=64][n=128] -> wt[n][k] (wt free after last KV GEMM)
        #pragma unroll 1
        for (int i = tid; i < 2048; i += NT) {
            const int k = i >> 5, ng = i & 31;
            float4 w = *(const float4*)(Wo + k * CZ + ng * 4);
            const int n = ng * 4;
            wt[(n + 0) * XST + k] = tf32r(w.x);
            wt[(n + 1) * XST + k] = tf32r(w.y);
            wt[(n + 2) * XST + k] = tf32r(w.z);
            wt[(n + 3) * XST + k] = tf32r(w.w);
        }
    }
    __syncthreads();

    {
        float oc[2][4][4] = {};
        gemm32(oc, xs, XST, wt, mt, nq, gid, tig, 8);
        #pragma unroll
        for (int f = 0; f < 2; f++) {
            const long r0 = base + mt * 32 + f * 16 + gid, r1 = r0 + 8;
            #pragma unroll
            for (int nt = 0; nt < 4; nt++) {
                const int c = nq * 32 + nt * 8 + tig * 2;
                if (r0 < R) {
                    float2 v = make_float2(oc[f][nt][0] + bos[c], oc[f][nt][1] + bos[c + 1]);
                    *(float2*)(out + r0 * (long)CZ + c) = v;
                }
                if (r1 < R) {
                    float2 v = make_float2(oc[f][nt][2] + bos[c], oc[f][nt][3] + bos[c + 1]);
                    *(float2*)(out + r1 * (long)CZ + c) = v;
                }
            }
        }
    }
}

extern "C" void kernel_launch(void* const* d_in, const int* in_sizes, int n_in,
                              void* d_out, int out_size)
{
    const float* tmpl = (const float*)d_in[0];
    const float* pair = (const float*)d_in[1];
    const float* lpg  = (const float*)d_in[2];
    const float* lpb  = (const float*)d_in[3];
    const float* ltg  = (const float*)d_in[4];
    const float* ltb  = (const float*)d_in[5];
    const float* Wq   = (const float*)d_in[6];
    const float* Wk   = (const float*)d_in[7];
    const float* Wv   = (const float*)d_in[8];
    const float* Wg   = (const float*)d_in[9];
    const float* bg   = (const float*)d_in[10];
    const float* Wo   = (const float*)d_in[11];
    const float* bo   = (const float*)d_in[12];
    float* out = (float*)d_out;

    const int R = in_sizes[1] / CZ;           // b*n*n pixels
    const int T = in_sizes[0] / in_sizes[1];  // templates

    const size_t smem = (size_t)(P * XST + 128 * XST + 3 * 256 + HD + CZ) * sizeof(float);
    cudaFuncSetAttribute(tpa_mma7, cudaFuncAttributeMaxDynamicSharedMemorySize, (int)smem);

    const int grid = (R + P - 1) / P;
    tpa_mma7<<<grid, NT, smem>>>(tmpl, pair, lpg, lpb, ltg, ltb,
                                 Wq, Wk, Wv, Wg, bg, Wo, bo, out, R, T);
}

// round 10
// speedup vs baseline: 1.0734x; 1.0734x over previous
#include <cuda_runtime.h>
#include <cstdint>

#define CZ  128
#define HD  64
#define P   128     // pixels per CTA
#define NT  512
#define XST 132     // [row][k] stride: scalar LDS banks 4*gid+tig -> conflict-free

static __device__ __forceinline__ float tf32r(float x) {
    float y; asm("cvt.rna.tf32.f32 %0, %1;" : "=f"(y) : "f"(x)); return y;
}

static __device__ __forceinline__ void mma8(float* d,
    float a0, float a1, float a2, float a3, float b0, float b1)
{
    asm volatile("mma.sync.aligned.m16n8k8.row.col.f32.tf32.tf32.f32 "
        "{%0,%1,%2,%3}, {%4,%5,%6,%7}, {%8,%9}, {%0,%1,%2,%3};"
        : "+f"(d[0]), "+f"(d[1]), "+f"(d[2]), "+f"(d[3])
        : "r"(__float_as_uint(a0)), "r"(__float_as_uint(a1)),
          "r"(__float_as_uint(a2)), "r"(__float_as_uint(a3)),
          "r"(__float_as_uint(b0)), "r"(__float_as_uint(b1)));
}

// Warp computes 32 rows (mt) x 32 cols (nq); K = 8*KT.
static __device__ __forceinline__ void gemm32(
    float acc[2][4][4], const float* A, int ast, const float* wt,
    int mt, int nq, int gid, int tig, int KT)
{
    const float* ar0 = A + (mt * 32 + gid) * ast + tig;
    const float* ar1 = ar0 + 8 * ast;
    const float* ar2 = ar0 + 16 * ast;
    const float* ar3 = ar0 + 24 * ast;
    const float* bp  = wt + (nq * 32 + gid) * XST + tig;
    #pragma unroll 4
    for (int kt = 0; kt < KT; kt++) {
        const int k0 = kt * 8;
        float a00 = ar0[k0], a01 = ar1[k0], a02 = ar0[k0 + 4], a03 = ar1[k0 + 4];
        float a10 = ar2[k0], a11 = ar3[k0], a12 = ar2[k0 + 4], a13 = ar3[k0 + 4];
        #pragma unroll
        for (int nt = 0; nt < 4; nt++) {
            float b0 = bp[nt * 8 * XST + k0];
            float b1 = bp[nt * 8 * XST + k0 + 4];
            mma8(acc[0][nt], a00, a01, a02, a03, b0, b1);
            mma8(acc[1][nt], a10, a11, a12, a13, b0, b1);
        }
    }
}

// LayerNorm rows r0, r0+step, ... of a 128x128 block -> tf32 [row][k] stride XST.
static __device__ __forceinline__ void ln128s(
    const float* __restrict__ src, long base, int R, float* dst,
    float4 g4, float4 b4, int r0, int step, int lane)
{
    const int c4 = lane * 4;
    #pragma unroll
    for (int r = r0; r < P; r += step) {
        long row = base + r;
        float4 x = make_float4(0.f, 0.f, 0.f, 0.f);
        if (row < R) x = *(const float4*)(src + row * (long)CZ + c4);
        float s = x.x + x.y + x.z + x.w;
        float q = fmaf(x.x, x.x, fmaf(x.y, x.y, fmaf(x.z, x.z, x.w * x.w)));
        #pragma unroll
        for (int o = 16; o; o >>= 1) {
            s += __shfl_xor_sync(0xffffffffu, s, o);
            q += __shfl_xor_sync(0xffffffffu, q, o);
        }
        float m  = s * (1.f / CZ);
        float v  = fmaxf(q * (1.f / CZ) - m * m, 0.f);
        float ri = rsqrtf(v + 1e-5f);
        float* xr = dst + r * XST + c4;
        xr[0] = tf32r((x.x - m) * ri * g4.x + b4.x);
        xr[1] = tf32r((x.y - m) * ri * g4.y + b4.y);
        xr[2] = tf32r((x.z - m) * ri * g4.z + b4.z);
        xr[3] = tf32r((x.w - m) * ri * g4.w + b4.w);
    }
}

// Stage two k-major [128][64] weights into wt[n][k] (n<64: W1, else W2).
static __device__ __forceinline__ void stageW2(
    float* wt, const float* __restrict__ W1, const float* __restrict__ W2, int tid)
{
    #pragma unroll 1
    for (int i = tid; i < 4096; i += NT) {
        const int m  = i >> 11;
        const int k  = (i >> 4) & 127;
        const int ng = i & 15;
        const float* Ws = m ? W2 : W1;
        float4 w = *(const float4*)(Ws + k * HD + ng * 4);
        const int n = m * 64 + ng * 4;
        wt[(n + 0) * XST + k] = tf32r(w.x);
        wt[(n + 1) * XST + k] = tf32r(w.y);
        wt[(n + 2) * XST + k] = tf32r(w.z);
        wt[(n + 3) * XST + k] = tf32r(w.w);
    }
}

__global__ void __launch_bounds__(NT, 1)
tpa_mma8(const float* __restrict__ tmpl, const float* __restrict__ pair,
         const float* __restrict__ lpg, const float* __restrict__ lpb,
         const float* __restrict__ ltg, const float* __restrict__ ltb,
         const float* __restrict__ Wq,  const float* __restrict__ Wk,
         const float* __restrict__ Wv,  const float* __restrict__ Wg,
         const float* __restrict__ bg,  const float* __restrict__ Wo,
         const float* __restrict__ bo,  float* __restrict__ out,
         int R, int T)
{
    extern __shared__ float smf[];
    float* xs0 = smf;                 // 128 x XST : LN buffer A
    float* xs1 = xs0 + P * XST;       // 128 x XST : LN buffer B
    float* wt  = xs1 + P * XST;       // 128 x XST : weights [n][k]
    float* rs0 = wt + 128 * XST;      // 512 : softmax rescale, parity 0   (p*4+h)
    float* ws0 = rs0 + 512;           // 512 : softmax weight,  parity 0
    float* rs1 = ws0 + 512;           // 512 : parity 1
    float* ws1 = rs1 + 512;           // 512 : parity 1
    float* ls  = ws1 + 512;           // 512 : 1/l
    float* bgs = ls + 512;            // 64
    float* bos = bgs + HD;            // 128

    const int tid  = threadIdx.x;
    const int lane = tid & 31;
    const int wid  = tid >> 5;
    const int mt   = wid & 3;         // m-tile (32 rows)
    const int nq   = wid >> 2;        // n quarter (32 cols)
    const int gid  = lane >> 2;
    const int tig  = lane & 3;
    const bool isK = (nq < 2);        // K-warps own Q/K cols; V-warps own G/V cols
    const long base = (long)blockIdx.x * P;

    if (tid < HD)  bgs[tid] = bg[tid];
    else if (tid >= 64 && tid < 64 + CZ) bos[tid - 64] = bo[tid - 64];

    const int c4 = lane * 4;
    const float4 gp = *(const float4*)(lpg + c4), bp = *(const float4*)(lpb + c4);
    const float4 gt = *(const float4*)(ltg + c4), bt = *(const float4*)(ltb + c4);

    // ---------------- Phase A: LN(pair)->xs0, Wq|Wg, QG GEMM ----------------
    ln128s(pair, base, R, xs0, gp, bp, wid, 16, lane);
    stageW2(wt, Wq, Wg, tid);
    __syncthreads();

    float qf[2][4][4] = {};           // K-warps: Q fragments; V-warps: G after sigmoid
    gemm32(qf, xs0, XST, wt, mt, nq, gid, tig, 16);
    if (!isK) {                       // sigmoid in place -> qf holds G
        #pragma unroll
        for (int f = 0; f < 2; f++)
            #pragma unroll
            for (int nt = 0; nt < 4; nt++) {
                const int c = (nq - 2) * 32 + nt * 8 + tig * 2;
                qf[f][nt][0] = 1.f / (1.f + __expf(-(qf[f][nt][0] + bgs[c])));
                qf[f][nt][1] = 1.f / (1.f + __expf(-(qf[f][nt][1] + bgs[c + 1])));
                qf[f][nt][2] = 1.f / (1.f + __expf(-(qf[f][nt][2] + bgs[c])));
                qf[f][nt][3] = 1.f / (1.f + __expf(-(qf[f][nt][3] + bgs[c + 1])));
            }
    }
    __syncthreads();                  // xs0/wt free

    // stage Wk|Wv; LN t0 -> xs0 (warps 0-7), LN t1 -> xs1 (warps 8-15)
    stageW2(wt, Wk, Wv, tid);
    if (wid < 8) ln128s(tmpl, base, R, xs0, gt, bt, wid, 8, lane);
    else if (T > 1) ln128s(tmpl + (long)R * CZ, base, R, xs1, gt, bt, wid - 8, 8, lane);

    float m8[8], l8[8];               // K-warp softmax state (tig==0 authoritative)
    #pragma unroll
    for (int i = 0; i < 8; i++) { m8[i] = __int_as_float(0xff800000); l8[i] = 0.f; }
    float vAcc[2][4][4] = {};
    __syncthreads();

    // ---------------- template loop: ONE sync per template ----------------
    #pragma unroll 1
    for (int t = 0; t < T; t++) {
        float* rsb = (t & 1) ? rs1 : rs0;
        float* wsb = (t & 1) ? ws1 : ws0;
        float kv[2][4][4] = {};
        gemm32(kv, (t & 1) ? xs1 : xs0, XST, wt, mt, nq, gid, tig, 16);

        if (isK) {                    // in-fragment scores + online softmax
            float sc[2][2][2];        // [f][rowhalf][headhalf]
            #pragma unroll
            for (int f = 0; f < 2; f++)
                #pragma unroll
                for (int hh = 0; hh < 2; hh++) {
                    const int nt0 = hh * 2;
                    #pragma unroll
                    for (int rh = 0; rh < 2; rh++) {
                        const int j = rh * 2;
                        float s = qf[f][nt0][j] * kv[f][nt0][j];
                        s = fmaf(qf[f][nt0][j + 1],     kv[f][nt0][j + 1],     s);
                        s = fmaf(qf[f][nt0 + 1][j],     kv[f][nt0 + 1][j],     s);
                        s = fmaf(qf[f][nt0 + 1][j + 1], kv[f][nt0 + 1][j + 1], s);
                        sc[f][rh][hh] = s;
                    }
                }
            #pragma unroll
            for (int f = 0; f < 2; f++)
                #pragma unroll
                for (int rh = 0; rh < 2; rh++)
                    #pragma unroll
                    for (int hh = 0; hh < 2; hh++) {
                        float v = sc[f][rh][hh];
                        v += __shfl_xor_sync(0xffffffffu, v, 1);
                        v += __shfl_xor_sync(0xffffffffu, v, 2);
                        sc[f][rh][hh] = v;
                    }
            if (tig == 0) {
                #pragma unroll
                for (int f = 0; f < 2; f++)
                    #pragma unroll
                    for (int rh = 0; rh < 2; rh++)
                        #pragma unroll
                        for (int hh = 0; hh < 2; hh++) {
                            const int i = f * 4 + rh * 2 + hh;
                            float sd = sc[f][rh][hh] * 0.25f;   // 1/sqrt(D=16)
                            float mn = fmaxf(m8[i], sd);
                            float rr = __expf(m8[i] - mn);
                            float ww = __expf(sd - mn);
                            l8[i] = l8[i] * rr + ww;
                            m8[i] = mn;
                            const int r = mt * 32 + f * 16 + rh * 8 + gid;
                            const int h = nq * 2 + hh;
                            rsb[r * 4 + h] = rr;
                            wsb[r * 4 + h] = ww;
                            if (t == T - 1)
                                ls[r * 4 + h] = 1.f / l8[i];
                        }
            }
        }
        __syncthreads();              // the ONE bar: rs/ws[t&1] + (last: ls) ready;
                                      // xs[t&1] fully read; prev V-acc complete

        if (!isK) {                   // V online accumulate (concurrent with K-warps'
                                      // next GEMM after they pass this bar)
            #pragma unroll
            for (int f = 0; f < 2; f++) {
                const int r0 = mt * 32 + f * 16 + gid, r1 = r0 + 8;
                #pragma unroll
                for (int nt = 0; nt < 4; nt++) {
                    const int h = ((nq - 2) * 32 + nt * 8) >> 4;
                    float rr0 = rsb[r0 * 4 + h], ww0 = wsb[r0 * 4 + h];
                    float rr1 = rsb[r1 * 4 + h], ww1 = wsb[r1 * 4 + h];
                    vAcc[f][nt][0] = fmaf(vAcc[f][nt][0], rr0, ww0 * kv[f][nt][0]);
                    vAcc[f][nt][1] = fmaf(vAcc[f][nt][1], rr0, ww0 * kv[f][nt][1]);
                    vAcc[f][nt][2] = fmaf(vAcc[f][nt][2], rr1, ww1 * kv[f][nt][2]);
                    vAcc[f][nt][3] = fmaf(vAcc[f][nt][3], rr1, ww1 * kv[f][nt][3]);
                }
            }
        }
        if (t + 2 < T)                // prefetch LN(t+2) into just-freed buffer
            ln128s(tmpl + (long)(t + 2) * R * CZ, base, R,
                   (t & 1) ? xs1 : xs0, gt, bt, wid, 16, lane);
        if (t == T - 1) {             // stage Wo (wt reads finished at the bar)
            #pragma unroll 1
            for (int i = tid; i < 2048; i += NT) {
                const int k = i >> 5, ng = i & 31;
                float4 w = *(const float4*)(Wo + k * CZ + ng * 4);
                const int n = ng * 4;
                wt[(n + 0) * XST + k] = tf32r(w.x);
                wt[(n + 1) * XST + k] = tf32r(w.y);
                wt[(n + 2) * XST + k] = tf32r(w.z);
                wt[(n + 3) * XST + k] = tf32r(w.w);
            }
        }
    }

    // ---------------- Phase C: vals -> xs[T&1], O GEMM ----------------
    float* xsv = (T & 1) ? xs1 : xs0;     // buffer NOT read by last GEMM
    if (!isK) {                           // vals = vAcc * G * linv (G lives in qf)
        #pragma unroll
        for (int f = 0; f < 2; f++) {
            const int r0 = mt * 32 + f * 16 + gid, r1 = r0 + 8;
            #pragma unroll
            for (int nt = 0; nt < 4; nt++) {
                const int c = (nq - 2) * 32 + nt * 8 + tig * 2;
                const int h = ((nq - 2) * 32 + nt * 8) >> 4;
                float li0 = ls[r0 * 4 + h], li1 = ls[r1 * 4 + h];
                xsv[r0 * XST + c]     = tf32r(vAcc[f][nt][0] * qf[f][nt][0] * li0);
                xsv[r0 * XST + c + 1] = tf32r(vAcc[f][nt][1] * qf[f][nt][1] * li0);
                xsv[r1 * XST + c]     = tf32r(vAcc[f][nt][2] * qf[f][nt][2] * li1);
                xsv[r1 * XST + c + 1] = tf32r(vAcc[f][nt][3] * qf[f][nt][3] * li1);
            }
        }
    }
    __syncthreads();                  // vals + Wo ready

    {
        float oc[2][4][4] = {};
        gemm32(oc, xsv, XST, wt, mt, nq, gid, tig, 8);
        #pragma unroll
        for (int f = 0; f < 2; f++) {
            const long r0 = base + mt * 32 + f * 16 + gid, r1 = r0 + 8;
            #pragma unroll
            for (int nt = 0; nt < 4; nt++) {
                const int c = nq * 32 + nt * 8 + tig * 2;
                if (r0 < R) {
                    float2 v = make_float2(oc[f][nt][0] + bos[c], oc[f][nt][1] + bos[c + 1]);
                    *(float2*)(out + r0 * (long)CZ + c) = v;
                }
                if (r1 < R) {
                    float2 v = make_float2(oc[f][nt][2] + bos[c], oc[f][nt][3] + bos[c + 1]);
                    *(float2*)(out + r1 * (long)CZ + c) = v;
                }
            }
        }
    }
}

extern "C" void kernel_launch(void* const* d_in, const int* in_sizes, int n_in,
                              void* d_out, int out_size)
{
    const float* tmpl = (const float*)d_in[0];
    const float* pair = (const float*)d_in[1];
    const float* lpg  = (const float*)d_in[2];
    const float* lpb  = (const float*)d_in[3];
    const float* ltg  = (const float*)d_in[4];
    const float* ltb  = (const float*)d_in[5];
    const float* Wq   = (const float*)d_in[6];
    const float* Wk   = (const float*)d_in[7];
    const float* Wv   = (const float*)d_in[8];
    const float* Wg   = (const float*)d_in[9];
    const float* bg   = (const float*)d_in[10];
    const float* Wo   = (const float*)d_in[11];
    const float* bo   = (const float*)d_in[12];
    float* out = (float*)d_out;

    const int R = in_sizes[1] / CZ;           // b*n*n pixels
    const int T = in_sizes[0] / in_sizes[1];  // templates

    const size_t smem = (size_t)(3 * P * XST + 5 * 512 + HD + CZ) * sizeof(float);
    cudaFuncSetAttribute(tpa_mma8, cudaFuncAttributeMaxDynamicSharedMemorySize, (int)smem);

    const int grid = (R + P - 1) / P;
    tpa_mma8<<<grid, NT, smem>>>(tmpl, pair, lpg, lpb, ltg, ltb,
                                 Wq, Wk, Wv, Wg, bg, Wo, bo, out, R, T);
}

// round 11
// speedup vs baseline: 1.3688x; 1.2752x over previous
#include <cuda_runtime.h>
#include <cuda_fp16.h>
#include <cstdint>

#define CZ   128
#define HD   64
#define P    128    // pixels per CTA
#define NT   512
#define XSTH 136    // halves per row: 136 % 64 == 8 -> LDS.32 banks (4*gid+tig), conflict-free

static __device__ __forceinline__ void mma16(float* d,
    uint32_t a0, uint32_t a1, uint32_t a2, uint32_t a3, uint32_t b0, uint32_t b1)
{
    asm volatile("mma.sync.aligned.m16n8k16.row.col.f32.f16.f16.f32 "
        "{%0,%1,%2,%3}, {%4,%5,%6,%7}, {%8,%9}, {%0,%1,%2,%3};"
        : "+f"(d[0]), "+f"(d[1]), "+f"(d[2]), "+f"(d[3])
        : "r"(a0), "r"(a1), "r"(a2), "r"(a3), "r"(b0), "r"(b1));
}

// Warp computes 32 rows (mt) x 32 cols (nq); K = 16*KT. A [row][k] halves stride ast,
// B wt[n][k] halves stride XSTH. Per k-step: 16 LDS.32 feed 8 MMAs (K=16 each).
static __device__ __forceinline__ void gemm32h(
    float acc[2][4][4], const __half* A, int ast, const __half* wt,
    int mt, int nq, int gid, int tig, int KT)
{
    const __half* ar = A + (mt * 32 + gid) * ast + tig * 2;
    const __half* bp = wt + (nq * 32 + gid) * XSTH + tig * 2;
    #pragma unroll
    for (int ks = 0; ks < KT; ks++) {
        const int k0 = ks * 16;
        uint32_t a00 = *(const uint32_t*)(ar + k0);
        uint32_t a01 = *(const uint32_t*)(ar + 8 * ast + k0);
        uint32_t a02 = *(const uint32_t*)(ar + k0 + 8);
        uint32_t a03 = *(const uint32_t*)(ar + 8 * ast + k0 + 8);
        uint32_t a10 = *(const uint32_t*)(ar + 16 * ast + k0);
        uint32_t a11 = *(const uint32_t*)(ar + 24 * ast + k0);
        uint32_t a12 = *(const uint32_t*)(ar + 16 * ast + k0 + 8);
        uint32_t a13 = *(const uint32_t*)(ar + 24 * ast + k0 + 8);
        #pragma unroll
        for (int nt = 0; nt < 4; nt++) {
            uint32_t b0 = *(const uint32_t*)(bp + nt * 8 * XSTH + k0);
            uint32_t b1 = *(const uint32_t*)(bp + nt * 8 * XSTH + k0 + 8);
            mma16(acc[0][nt], a00, a01, a02, a03, b0, b1);
            mma16(acc[1][nt], a10, a11, a12, a13, b0, b1);
        }
    }
}

// LayerNorm rows r0, r0+step, ... of a 128x128 block -> fp16 [row][k] stride XSTH.
static __device__ __forceinline__ void ln128s(
    const float* __restrict__ src, long base, int R, __half* dst,
    float4 g4, float4 b4, int r0, int step, int lane)
{
    const int c4 = lane * 4;
    #pragma unroll
    for (int r = r0; r < P; r += step) {
        long row = base + r;
        float4 x = make_float4(0.f, 0.f, 0.f, 0.f);
        if (row < R) x = *(const float4*)(src + row * (long)CZ + c4);
        float s = x.x + x.y + x.z + x.w;
        float q = fmaf(x.x, x.x, fmaf(x.y, x.y, fmaf(x.z, x.z, x.w * x.w)));
        #pragma unroll
        for (int o = 16; o; o >>= 1) {
            s += __shfl_xor_sync(0xffffffffu, s, o);
            q += __shfl_xor_sync(0xffffffffu, q, o);
        }
        float m  = s * (1.f / CZ);
        float v  = fmaxf(q * (1.f / CZ) - m * m, 0.f);
        float ri = rsqrtf(v + 1e-5f);
        __half* xr = dst + r * XSTH + c4;
        *(__half2*)(xr)     = __floats2half2_rn((x.x - m) * ri * g4.x + b4.x,
                                                (x.y - m) * ri * g4.y + b4.y);
        *(__half2*)(xr + 2) = __floats2half2_rn((x.z - m) * ri * g4.z + b4.z,
                                                (x.w - m) * ri * g4.w + b4.w);
    }
}

// Stage two k-major [128][64] weights into wt[n][k] fp16 (n<64: W1, else W2).
static __device__ __forceinline__ void stageW2(
    __half* wt, const float* __restrict__ W1, const float* __restrict__ W2, int tid)
{
    #pragma unroll 1
    for (int i = tid; i < 4096; i += NT) {
        const int m  = i >> 11;
        const int k  = (i >> 4) & 127;
        const int ng = i & 15;
        const float* Ws = m ? W2 : W1;
        float4 w = *(const float4*)(Ws + k * HD + ng * 4);
        const int n = m * 64 + ng * 4;
        wt[(n + 0) * XSTH + k] = __float2half_rn(w.x);
        wt[(n + 1) * XSTH + k] = __float2half_rn(w.y);
        wt[(n + 2) * XSTH + k] = __float2half_rn(w.z);
        wt[(n + 3) * XSTH + k] = __float2half_rn(w.w);
    }
}

__global__ void __launch_bounds__(NT, 1)
tpa_mma9(const float* __restrict__ tmpl, const float* __restrict__ pair,
         const float* __restrict__ lpg, const float* __restrict__ lpb,
         const float* __restrict__ ltg, const float* __restrict__ ltb,
         const float* __restrict__ Wq,  const float* __restrict__ Wk,
         const float* __restrict__ Wv,  const float* __restrict__ Wg,
         const float* __restrict__ bg,  const float* __restrict__ Wo,
         const float* __restrict__ bo,  float* __restrict__ out,
         int R, int T)
{
    extern __shared__ __align__(16) char smc[];
    __half* xs0 = (__half*)smc;               // 128 x XSTH halves : LN buffer A
    __half* xs1 = xs0 + P * XSTH;             // 128 x XSTH : LN buffer B
    __half* wt  = xs1 + P * XSTH;             // 128 x XSTH : weights [n][k]
    float*  rs0 = (float*)(wt + P * XSTH);    // 512 : softmax rescale, parity 0 (p*4+h)
    float*  ws0 = rs0 + 512;                  // 512
    float*  rs1 = ws0 + 512;                  // 512 : parity 1
    float*  ws1 = rs1 + 512;                  // 512
    float*  ls  = ws1 + 512;                  // 512 : 1/l
    float*  bgs = ls + 512;                   // 64
    float*  bos = bgs + HD;                   // 128

    const int tid  = threadIdx.x;
    const int lane = tid & 31;
    const int wid  = tid >> 5;
    const int mt   = wid & 3;         // m-tile (32 rows)
    const int nq   = wid >> 2;        // n quarter (32 cols)
    const int gid  = lane >> 2;
    const int tig  = lane & 3;
    const bool isK = (nq < 2);        // K-warps own Q/K cols; V-warps own G/V cols
    const long base = (long)blockIdx.x * P;

    if (tid < HD)  bgs[tid] = bg[tid];
    else if (tid >= 64 && tid < 64 + CZ) bos[tid - 64] = bo[tid - 64];

    const int c4 = lane * 4;
    const float4 gp = *(const float4*)(lpg + c4), bp = *(const float4*)(lpb + c4);
    const float4 gt = *(const float4*)(ltg + c4), bt = *(const float4*)(ltb + c4);

    // ---------------- Phase A: LN(pair)->xs0, Wq|Wg, QG GEMM ----------------
    ln128s(pair, base, R, xs0, gp, bp, wid, 16, lane);
    stageW2(wt, Wq, Wg, tid);
    __syncthreads();

    float qf[2][4][4] = {};           // K-warps: Q fragments; V-warps: G after sigmoid
    gemm32h(qf, xs0, XSTH, wt, mt, nq, gid, tig, 8);
    if (!isK) {                       // sigmoid in place -> qf holds G
        #pragma unroll
        for (int f = 0; f < 2; f++)
            #pragma unroll
            for (int nt = 0; nt < 4; nt++) {
                const int c = (nq - 2) * 32 + nt * 8 + tig * 2;
                qf[f][nt][0] = 1.f / (1.f + __expf(-(qf[f][nt][0] + bgs[c])));
                qf[f][nt][1] = 1.f / (1.f + __expf(-(qf[f][nt][1] + bgs[c + 1])));
                qf[f][nt][2] = 1.f / (1.f + __expf(-(qf[f][nt][2] + bgs[c])));
                qf[f][nt][3] = 1.f / (1.f + __expf(-(qf[f][nt][3] + bgs[c + 1])));
            }
    }
    __syncthreads();                  // xs0/wt free

    // stage Wk|Wv; LN t0 -> xs0 (warps 0-7), LN t1 -> xs1 (warps 8-15)
    stageW2(wt, Wk, Wv, tid);
    if (wid < 8) ln128s(tmpl, base, R, xs0, gt, bt, wid, 8, lane);
    else if (T > 1) ln128s(tmpl + (long)R * CZ, base, R, xs1, gt, bt, wid - 8, 8, lane);

    float m8[8], l8[8];               // K-warp softmax state (tig==0 authoritative)
    #pragma unroll
    for (int i = 0; i < 8; i++) { m8[i] = __int_as_float(0xff800000); l8[i] = 0.f; }
    float vAcc[2][4][4] = {};
    __syncthreads();

    // ---------------- template loop: ONE sync per template ----------------
    #pragma unroll 1
    for (int t = 0; t < T; t++) {
        float* rsb = (t & 1) ? rs1 : rs0;
        float* wsb = (t & 1) ? ws1 : ws0;
        float kv[2][4][4] = {};
        gemm32h(kv, (t & 1) ? xs1 : xs0, XSTH, wt, mt, nq, gid, tig, 8);

        if (isK) {                    // in-fragment scores + online softmax
            float sc[2][2][2];        // [f][rowhalf][headhalf]
            #pragma unroll
            for (int f = 0; f < 2; f++)
                #pragma unroll
                for (int hh = 0; hh < 2; hh++) {
                    const int nt0 = hh * 2;
                    #pragma unroll
                    for (int rh = 0; rh < 2; rh++) {
                        const int j = rh * 2;
                        float s = qf[f][nt0][j] * kv[f][nt0][j];
                        s = fmaf(qf[f][nt0][j + 1],     kv[f][nt0][j + 1],     s);
                        s = fmaf(qf[f][nt0 + 1][j],     kv[f][nt0 + 1][j],     s);
                        s = fmaf(qf[f][nt0 + 1][j + 1], kv[f][nt0 + 1][j + 1], s);
                        sc[f][rh][hh] = s;
                    }
                }
            #pragma unroll
            for (int f = 0; f < 2; f++)
                #pragma unroll
                for (int rh = 0; rh < 2; rh++)
                    #pragma unroll
                    for (int hh = 0; hh < 2; hh++) {
                        float v = sc[f][rh][hh];
                        v += __shfl_xor_sync(0xffffffffu, v, 1);
                        v += __shfl_xor_sync(0xffffffffu, v, 2);
                        sc[f][rh][hh] = v;
                    }
            if (tig == 0) {
                #pragma unroll
                for (int f = 0; f < 2; f++)
                    #pragma unroll
                    for (int rh = 0; rh < 2; rh++)
                        #pragma unroll
                        for (int hh = 0; hh < 2; hh++) {
                            const int i = f * 4 + rh * 2 + hh;
                            float sd = sc[f][rh][hh] * 0.25f;   // 1/sqrt(D=16)
                            float mn = fmaxf(m8[i], sd);
                            float rr = __expf(m8[i] - mn);
                            float ww = __expf(sd - mn);
                            l8[i] = l8[i] * rr + ww;
                            m8[i] = mn;
                            const int r = mt * 32 + f * 16 + rh * 8 + gid;
                            const int h = nq * 2 + hh;
                            rsb[r * 4 + h] = rr;
                            wsb[r * 4 + h] = ww;
                            if (t == T - 1)
                                ls[r * 4 + h] = 1.f / l8[i];
                        }
            }
        }
        __syncthreads();              // rs/ws[t&1] (+ last: ls) ready; xs[t&1] read done

        if (!isK) {                   // V online accumulate
            #pragma unroll
            for (int f = 0; f < 2; f++) {
                const int r0 = mt * 32 + f * 16 + gid, r1 = r0 + 8;
                #pragma unroll
                for (int nt = 0; nt < 4; nt++) {
                    const int h = ((nq - 2) * 32 + nt * 8) >> 4;
                    float rr0 = rsb[r0 * 4 + h], ww0 = wsb[r0 * 4 + h];
                    float rr1 = rsb[r1 * 4 + h], ww1 = wsb[r1 * 4 + h];
                    vAcc[f][nt][0] = fmaf(vAcc[f][nt][0], rr0, ww0 * kv[f][nt][0]);
                    vAcc[f][nt][1] = fmaf(vAcc[f][nt][1], rr0, ww0 * kv[f][nt][1]);
                    vAcc[f][nt][2] = fmaf(vAcc[f][nt][2], rr1, ww1 * kv[f][nt][2]);
                    vAcc[f][nt][3] = fmaf(vAcc[f][nt][3], rr1, ww1 * kv[f][nt][3]);
                }
            }
        }
        if (t + 2 < T)                // prefetch LN(t+2) into just-freed buffer
            ln128s(tmpl + (long)(t + 2) * R * CZ, base, R,
                   (t & 1) ? xs1 : xs0, gt, bt, wid, 16, lane);
        if (t == T - 1) {             // stage Wo[k=64][n=128] -> wt[n][k]
            #pragma unroll 1
            for (int i = tid; i < 2048; i += NT) {
                const int k = i >> 5, ng = i & 31;
                float4 w = *(const float4*)(Wo + k * CZ + ng * 4);
                const int n = ng * 4;
                wt[(n + 0) * XSTH + k] = __float2half_rn(w.x);
                wt[(n + 1) * XSTH + k] = __float2half_rn(w.y);
                wt[(n + 2) * XSTH + k] = __float2half_rn(w.z);
                wt[(n + 3) * XSTH + k] = __float2half_rn(w.w);
            }
        }
    }

    // ---------------- Phase C: vals -> xs[T&1], O GEMM ----------------
    __half* xsv = (T & 1) ? xs1 : xs0;    // buffer NOT read by last GEMM
    if (!isK) {                           // vals = vAcc * G * linv (G lives in qf)
        #pragma unroll
        for (int f = 0; f < 2; f++) {
            const int r0 = mt * 32 + f * 16 + gid, r1 = r0 + 8;
            #pragma unroll
            for (int nt = 0; nt < 4; nt++) {
                const int c = (nq - 2) * 32 + nt * 8 + tig * 2;
                const int h = ((nq - 2) * 32 + nt * 8) >> 4;
                float li0 = ls[r0 * 4 + h], li1 = ls[r1 * 4 + h];
                *(__half2*)(xsv + r0 * XSTH + c) =
                    __floats2half2_rn(vAcc[f][nt][0] * qf[f][nt][0] * li0,
                                      vAcc[f][nt][1] * qf[f][nt][1] * li0);
                *(__half2*)(xsv + r1 * XSTH + c) =
                    __floats2half2_rn(vAcc[f][nt][2] * qf[f][nt][2] * li1,
                                      vAcc[f][nt][3] * qf[f][nt][3] * li1);
            }
        }
    }
    __syncthreads();                  // vals + Wo ready

    {
        float oc[2][4][4] = {};
        gemm32h(oc, xsv, XSTH, wt, mt, nq, gid, tig, 4);
        #pragma unroll
        for (int f = 0; f < 2; f++) {
            const long r0 = base + mt * 32 + f * 16 + gid, r1 = r0 + 8;
            #pragma unroll
            for (int nt = 0; nt < 4; nt++) {
                const int c = nq * 32 + nt * 8 + tig * 2;
                if (r0 < R) {
                    float2 v = make_float2(oc[f][nt][0] + bos[c], oc[f][nt][1] + bos[c + 1]);
                    *(float2*)(out + r0 * (long)CZ + c) = v;
                }
                if (r1 < R) {
                    float2 v = make_float2(oc[f][nt][2] + bos[c], oc[f][nt][3] + bos[c + 1]);
                    *(float2*)(out + r1 * (long)CZ + c) = v;
                }
            }
        }
    }
}

extern "C" void kernel_launch(void* const* d_in, const int* in_sizes, int n_in,
                              void* d_out, int out_size)
{
    const float* tmpl = (const float*)d_in[0];
    const float* pair = (const float*)d_in[1];
    const float* lpg  = (const float*)d_in[2];
    const float* lpb  = (const float*)d_in[3];
    const float* ltg  = (const float*)d_in[4];
    const float* ltb  = (const float*)d_in[5];
    const float* Wq   = (const float*)d_in[6];
    const float* Wk   = (const float*)d_in[7];
    const float* Wv   = (const float*)d_in[8];
    const float* Wg   = (const float*)d_in[9];
    const float* bg   = (const float*)d_in[10];
    const float* Wo   = (const float*)d_in[11];
    const float* bo   = (const float*)d_in[12];
    float* out = (float*)d_out;

    const int R = in_sizes[1] / CZ;           // b*n*n pixels
    const int T = in_sizes[0] / in_sizes[1];  // templates

    const size_t smem = (size_t)(3 * P * XSTH) * sizeof(__half)
                      + (size_t)(5 * 512 + HD + CZ) * sizeof(float);
    cudaFuncSetAttribute(tpa_mma9, cudaFuncAttributeMaxDynamicSharedMemorySize, (int)smem);

    const int grid = (R + P - 1) / P;
    tpa_mma9<<<grid, NT, smem>>>(tmpl, pair, lpg, lpb, ltg, ltb,
                                 Wq, Wk, Wv, Wg, bg, Wo, bo, out, R, T);
}

// round 12
// speedup vs baseline: 1.4073x; 1.0281x over previous
#include <cuda_runtime.h>
#include <cuda_fp16.h>
#include <cstdint>

#define CZ   128
#define HD   64
#define P    128    // pixels per CTA
#define NT   1024
#define NW   32
#define XSTH 136    // halves per row: LDS banks (4*gid+tig) -> conflict-free
#define GST  72     // halves per row of G-gate tile

static __device__ __forceinline__ void mma16(float* d,
    uint32_t a0, uint32_t a1, uint32_t a2, uint32_t a3, uint32_t b0, uint32_t b1)
{
    asm volatile("mma.sync.aligned.m16n8k16.row.col.f32.f16.f16.f32 "
        "{%0,%1,%2,%3}, {%4,%5,%6,%7}, {%8,%9}, {%0,%1,%2,%3};"
        : "+f"(d[0]), "+f"(d[1]), "+f"(d[2]), "+f"(d[3])
        : "r"(a0), "r"(a1), "r"(a2), "r"(a3), "r"(b0), "r"(b1));
}

// Warp computes 16 rows (mt of 8) x 32 cols (nq of 4); K = 16*KT halves.
static __device__ __forceinline__ void gemm16(
    float acc[4][4], const __half* A, int ast, const __half* wt,
    int mt, int nq, int gid, int tig, int KT)
{
    const __half* ar = A + (mt * 16 + gid) * ast + tig * 2;
    const __half* bp = wt + (nq * 32 + gid) * XSTH + tig * 2;
    #pragma unroll
    for (int ks = 0; ks < KT; ks++) {
        const int k0 = ks * 16;
        uint32_t a0 = *(const uint32_t*)(ar + k0);
        uint32_t a1 = *(const uint32_t*)(ar + 8 * ast + k0);
        uint32_t a2 = *(const uint32_t*)(ar + k0 + 8);
        uint32_t a3 = *(const uint32_t*)(ar + 8 * ast + k0 + 8);
        #pragma unroll
        for (int nt = 0; nt < 4; nt++) {
            uint32_t b0 = *(const uint32_t*)(bp + nt * 8 * XSTH + k0);
            uint32_t b1 = *(const uint32_t*)(bp + nt * 8 * XSTH + k0 + 8);
            mma16(acc[nt], a0, a1, a2, a3, b0, b1);
        }
    }
}

// LayerNorm rows r0, r0+step, ... -> fp16 [row][k] stride XSTH. g/b loaded per call.
static __device__ __forceinline__ void ln128s(
    const float* __restrict__ src, long base, int R, __half* dst,
    const float* __restrict__ g, const float* __restrict__ b,
    int r0, int step, int lane)
{
    const int c4 = lane * 4;
    const float4 g4 = *(const float4*)(g + c4);
    const float4 b4 = *(const float4*)(b + c4);
    #pragma unroll
    for (int r = r0; r < P; r += step) {
        long row = base + r;
        float4 x = make_float4(0.f, 0.f, 0.f, 0.f);
        if (row < R) x = *(const float4*)(src + row * (long)CZ + c4);
        float s = x.x + x.y + x.z + x.w;
        float q = fmaf(x.x, x.x, fmaf(x.y, x.y, fmaf(x.z, x.z, x.w * x.w)));
        #pragma unroll
        for (int o = 16; o; o >>= 1) {
            s += __shfl_xor_sync(0xffffffffu, s, o);
            q += __shfl_xor_sync(0xffffffffu, q, o);
        }
        float m  = s * (1.f / CZ);
        float v  = fmaxf(q * (1.f / CZ) - m * m, 0.f);
        float ri = rsqrtf(v + 1e-5f);
        __half* xr = dst + r * XSTH + c4;
        *(__half2*)(xr)     = __floats2half2_rn((x.x - m) * ri * g4.x + b4.x,
                                                (x.y - m) * ri * g4.y + b4.y);
        *(__half2*)(xr + 2) = __floats2half2_rn((x.z - m) * ri * g4.z + b4.z,
                                                (x.w - m) * ri * g4.w + b4.w);
    }
}

// Stage two k-major [128][64] weights into wt[n][k] fp16 (n<64: W1, else W2).
static __device__ __forceinline__ void stageW2(
    __half* wt, const float* __restrict__ W1, const float* __restrict__ W2, int tid)
{
    #pragma unroll 1
    for (int i = tid; i < 4096; i += NT) {
        const int m  = i >> 11;
        const int k  = (i >> 4) & 127;
        const int ng = i & 15;
        const float* Ws = m ? W2 : W1;
        float4 w = *(const float4*)(Ws + k * HD + ng * 4);
        const int n = m * 64 + ng * 4;
        wt[(n + 0) * XSTH + k] = __float2half_rn(w.x);
        wt[(n + 1) * XSTH + k] = __float2half_rn(w.y);
        wt[(n + 2) * XSTH + k] = __float2half_rn(w.z);
        wt[(n + 3) * XSTH + k] = __float2half_rn(w.w);
    }
}

__global__ void __launch_bounds__(NT, 1)
tpa_mma10(const float* __restrict__ tmpl, const float* __restrict__ pair,
          const float* __restrict__ lpg, const float* __restrict__ lpb,
          const float* __restrict__ ltg, const float* __restrict__ ltb,
          const float* __restrict__ Wq,  const float* __restrict__ Wk,
          const float* __restrict__ Wv,  const float* __restrict__ Wg,
          const float* __restrict__ bg,  const float* __restrict__ Wo,
          const float* __restrict__ bo,  float* __restrict__ out,
          int R, int T)
{
    extern __shared__ __align__(16) char smc[];
    __half* xs0 = (__half*)smc;               // 128 x XSTH : LN buffer A
    __half* xs1 = xs0 + P * XSTH;             // 128 x XSTH : LN buffer B
    __half* wt  = xs1 + P * XSTH;             // 128 x XSTH : weights [n][k]
    __half* gs  = wt + P * XSTH;              // 128 x GST  : G gate (fp16)
    float*  rs0 = (float*)(gs + P * GST);     // 512 : rescale parity 0 (p*4+h)
    float*  ws0 = rs0 + 512;                  // 512
    float*  rs1 = ws0 + 512;                  // 512 : parity 1
    float*  ws1 = rs1 + 512;                  // 512
    float*  ls  = ws1 + 512;                  // 512 : 1/l
    float*  bgs = ls + 512;                   // 64
    float*  bos = bgs + HD;                   // 128

    const int tid  = threadIdx.x;
    const int lane = tid & 31;
    const int wid  = tid >> 5;
    const int mt   = wid & 7;         // m-tile (16 rows)
    const int nq   = wid >> 3;        // n quarter (32 cols)
    const int gid  = lane >> 2;
    const int tig  = lane & 3;
    const bool isK = (nq < 2);
    const long base = (long)blockIdx.x * P;

    if (tid < HD)  bgs[tid] = bg[tid];
    else if (tid >= 64 && tid < 64 + CZ) bos[tid - 64] = bo[tid - 64];

    // ---------------- Phase A: LN(pair)->xs0, Wq|Wg, QG GEMM ----------------
    ln128s(pair, base, R, xs0, lpg, lpb, wid, NW, lane);
    stageW2(wt, Wq, Wg, tid);
    __syncthreads();

    float qf[4][4] = {};              // K-warps keep Q; V-warps: temp for G
    gemm16(qf, xs0, XSTH, wt, mt, nq, gid, tig, 8);
    if (!isK) {                       // sigmoid -> gs (fp16), qf dead afterwards
        const int r0 = mt * 16 + gid, r1 = r0 + 8;
        #pragma unroll
        for (int nt = 0; nt < 4; nt++) {
            const int c = (nq - 2) * 32 + nt * 8 + tig * 2;
            float g0 = 1.f / (1.f + __expf(-(qf[nt][0] + bgs[c])));
            float g1 = 1.f / (1.f + __expf(-(qf[nt][1] + bgs[c + 1])));
            float g2 = 1.f / (1.f + __expf(-(qf[nt][2] + bgs[c])));
            float g3 = 1.f / (1.f + __expf(-(qf[nt][3] + bgs[c + 1])));
            *(__half2*)(gs + r0 * GST + c) = __floats2half2_rn(g0, g1);
            *(__half2*)(gs + r1 * GST + c) = __floats2half2_rn(g2, g3);
        }
    }
    __syncthreads();                  // xs0/wt reads done

    // stage Wk|Wv; LN t0 -> xs0 (warps 0-15), LN t1 -> xs1 (warps 16-31)
    stageW2(wt, Wk, Wv, tid);
    if (wid < 16) ln128s(tmpl, base, R, xs0, ltg, ltb, wid, 16, lane);
    else if (T > 1) ln128s(tmpl + (long)R * CZ, base, R, xs1, ltg, ltb, wid - 16, 16, lane);

    // pv: K-warps -> m4 = pv[0..3], l4 = pv[4..7]; V-warps -> vAcc[nt][j] = pv[nt*4+j]
    float pv[16];
    #pragma unroll
    for (int i = 0; i < 16; i++) pv[i] = 0.f;
    if (isK) {
        #pragma unroll
        for (int i = 0; i < 4; i++) pv[i] = __int_as_float(0xff800000);
    }
    __syncthreads();

    // ---------------- template loop: ONE sync per template ----------------
    #pragma unroll 1
    for (int t = 0; t < T; t++) {
        float* rsb = (t & 1) ? rs1 : rs0;
        float* wsb = (t & 1) ? ws1 : ws0;
        float kv[4][4] = {};
        gemm16(kv, (t & 1) ? xs1 : xs0, XSTH, wt, mt, nq, gid, tig, 8);

        if (isK) {                    // in-fragment scores + online softmax
            float sc[2][2];           // [rowhalf][headhalf]
            #pragma unroll
            for (int hh = 0; hh < 2; hh++) {
                const int nt0 = hh * 2;
                #pragma unroll
                for (int rh = 0; rh < 2; rh++) {
                    const int j = rh * 2;
                    float s = qf[nt0][j] * kv[nt0][j];
                    s = fmaf(qf[nt0][j + 1],     kv[nt0][j + 1],     s);
                    s = fmaf(qf[nt0 + 1][j],     kv[nt0 + 1][j],     s);
                    s = fmaf(qf[nt0 + 1][j + 1], kv[nt0 + 1][j + 1], s);
                    sc[rh][hh] = s;
                }
            }
            #pragma unroll
            for (int rh = 0; rh < 2; rh++)
                #pragma unroll
                for (int hh = 0; hh < 2; hh++) {
                    float v = sc[rh][hh];
                    v += __shfl_xor_sync(0xffffffffu, v, 1);
                    v += __shfl_xor_sync(0xffffffffu, v, 2);
                    sc[rh][hh] = v;
                }
            if (tig == 0) {
                #pragma unroll
                for (int rh = 0; rh < 2; rh++)
                    #pragma unroll
                    for (int hh = 0; hh < 2; hh++) {
                        const int i = rh * 2 + hh;
                        float sd = sc[rh][hh] * 0.25f;    // 1/sqrt(D=16)
                        float mn = fmaxf(pv[i], sd);
                        float rr = __expf(pv[i] - mn);
                        float ww = __expf(sd - mn);
                        pv[4 + i] = pv[4 + i] * rr + ww;
                        pv[i] = mn;
                        const int r = mt * 16 + rh * 8 + gid;
                        const int h = nq * 2 + hh;
                        rsb[r * 4 + h] = rr;
                        wsb[r * 4 + h] = ww;
                        if (t == T - 1)
                            ls[r * 4 + h] = 1.f / pv[4 + i];
                    }
            }
        }
        __syncthreads();              // rs/ws[t&1] (+ last: ls) ready; xs[t&1] read done

        if (!isK) {                   // V online accumulate into pv
            const int r0 = mt * 16 + gid, r1 = r0 + 8;
            #pragma unroll
            for (int nt = 0; nt < 4; nt++) {
                const int h = (nq - 2) * 2 + (nt >> 1);
                float rr0 = rsb[r0 * 4 + h], ww0 = wsb[r0 * 4 + h];
                float rr1 = rsb[r1 * 4 + h], ww1 = wsb[r1 * 4 + h];
                pv[nt * 4 + 0] = fmaf(pv[nt * 4 + 0], rr0, ww0 * kv[nt][0]);
                pv[nt * 4 + 1] = fmaf(pv[nt * 4 + 1], rr0, ww0 * kv[nt][1]);
                pv[nt * 4 + 2] = fmaf(pv[nt * 4 + 2], rr1, ww1 * kv[nt][2]);
                pv[nt * 4 + 3] = fmaf(pv[nt * 4 + 3], rr1, ww1 * kv[nt][3]);
            }
        }
        if (t + 2 < T)                // prefetch LN(t+2) into just-freed buffer
            ln128s(tmpl + (long)(t + 2) * R * CZ, base, R,
                   (t & 1) ? xs1 : xs0, ltg, ltb, wid, NW, lane);
        if (t == T - 1) {             // stage Wo[k=64][n=128] -> wt[n][k]
            #pragma unroll 1
            for (int i = tid; i < 2048; i += NT) {
                const int k = i >> 5, ng = i & 31;
                float4 w = *(const float4*)(Wo + k * CZ + ng * 4);
                const int n = ng * 4;
                wt[(n + 0) * XSTH + k] = __float2half_rn(w.x);
                wt[(n + 1) * XSTH + k] = __float2half_rn(w.y);
                wt[(n + 2) * XSTH + k] = __float2half_rn(w.z);
                wt[(n + 3) * XSTH + k] = __float2half_rn(w.w);
            }
        }
    }

    // ---------------- Phase C: vals -> xs[T&1], O GEMM ----------------
    __half* xsv = (T & 1) ? xs1 : xs0;    // buffer NOT read by last GEMM
    if (!isK) {                           // vals = vAcc * G * linv
        const int r0 = mt * 16 + gid, r1 = r0 + 8;
        #pragma unroll
        for (int nt = 0; nt < 4; nt++) {
            const int c = (nq - 2) * 32 + nt * 8 + tig * 2;
            const int h = (nq - 2) * 2 + (nt >> 1);
            float li0 = ls[r0 * 4 + h], li1 = ls[r1 * 4 + h];
            float2 g0 = __half22float2(*(__half2*)(gs + r0 * GST + c));
            float2 g1 = __half22float2(*(__half2*)(gs + r1 * GST + c));
            *(__half2*)(xsv + r0 * XSTH + c) =
                __floats2half2_rn(pv[nt * 4 + 0] * g0.x * li0,
                                  pv[nt * 4 + 1] * g0.y * li0);
            *(__half2*)(xsv + r1 * XSTH + c) =
                __floats2half2_rn(pv[nt * 4 + 2] * g1.x * li1,
                                  pv[nt * 4 + 3] * g1.y * li1);
        }
    }
    __syncthreads();                  // vals + Wo ready

    {
        float oc[4][4] = {};
        gemm16(oc, xsv, XSTH, wt, mt, nq, gid, tig, 4);
        const long r0 = base + mt * 16 + gid, r1 = r0 + 8;
        #pragma unroll
        for (int nt = 0; nt < 4; nt++) {
            const int c = nq * 32 + nt * 8 + tig * 2;
            if (r0 < R) {
                float2 v = make_float2(oc[nt][0] + bos[c], oc[nt][1] + bos[c + 1]);
                *(float2*)(out + r0 * (long)CZ + c) = v;
            }
            if (r1 < R) {
                float2 v = make_float2(oc[nt][2] + bos[c], oc[nt][3] + bos[c + 1]);
                *(float2*)(out + r1 * (long)CZ + c) = v;
            }
        }
    }
}

extern "C" void kernel_launch(void* const* d_in, const int* in_sizes, int n_in,
                              void* d_out, int out_size)
{
    const float* tmpl = (const float*)d_in[0];
    const float* pair = (const float*)d_in[1];
    const float* lpg  = (const float*)d_in[2];
    const float* lpb  = (const float*)d_in[3];
    const float* ltg  = (const float*)d_in[4];
    const float* ltb  = (const float*)d_in[5];
    const float* Wq   = (const float*)d_in[6];
    const float* Wk   = (const float*)d_in[7];
    const float* Wv   = (const float*)d_in[8];
    const float* Wg   = (const float*)d_in[9];
    const float* bg   = (const float*)d_in[10];
    const float* Wo   = (const float*)d_in[11];
    const float* bo   = (const float*)d_in[12];
    float* out = (float*)d_out;

    const int R = in_sizes[1] / CZ;           // b*n*n pixels
    const int T = in_sizes[0] / in_sizes[1];  // templates

    const size_t smem = (size_t)(3 * P * XSTH + P * GST) * sizeof(__half)
                      + (size_t)(5 * 512 + HD + CZ) * sizeof(float);
    cudaFuncSetAttribute(tpa_mma10, cudaFuncAttributeMaxDynamicSharedMemorySize, (int)smem);

    const int grid = (R + P - 1) / P;
    tpa_mma10<<<grid, NT, smem>>>(tmpl, pair, lpg, lpb, ltg, ltb,
                                  Wq, Wk, Wv, Wg, bg, Wo, bo, out, R, T);
}

// round 13
// speedup vs baseline: 1.4499x; 1.0303x over previous
#include <cuda_runtime.h>
#include <cuda_fp16.h>
#include <cstdint>

#define CZ   128
#define HD   64
#define P    128    // pixels per CTA
#define NT   1024
#define NW   32
#define XSTH 136    // halves per row: 272B stride -> ldmatrix 8-row fetches conflict-free
#define GST  72     // halves per row of G-gate tile

static __device__ __forceinline__ uint32_t smem_u32(const void* p) {
    return (uint32_t)__cvta_generic_to_shared(p);
}

static __device__ __forceinline__ void mma16(float* d,
    uint32_t a0, uint32_t a1, uint32_t a2, uint32_t a3, uint32_t b0, uint32_t b1)
{
    asm volatile("mma.sync.aligned.m16n8k16.row.col.f32.f16.f16.f32 "
        "{%0,%1,%2,%3}, {%4,%5,%6,%7}, {%8,%9}, {%0,%1,%2,%3};"
        : "+f"(d[0]), "+f"(d[1]), "+f"(d[2]), "+f"(d[3])
        : "r"(a0), "r"(a1), "r"(a2), "r"(a3), "r"(b0), "r"(b1));
}

static __device__ __forceinline__ void ldm4(
    uint32_t& r0, uint32_t& r1, uint32_t& r2, uint32_t& r3, uint32_t addr)
{
    asm volatile("ldmatrix.sync.aligned.m8n8.x4.shared.b16 {%0,%1,%2,%3}, [%4];"
        : "=r"(r0), "=r"(r1), "=r"(r2), "=r"(r3) : "r"(addr));
}

// Warp computes 16 rows x 32 cols; K = 16*KT halves. aAddr/bAddr are lane-resolved
// shared-space byte addresses of the warp's A / B tiles at k=0.
// Per k-step: 1 A-ldmatrix.x4 + 2 B-ldmatrix.x4 feed 4 MMAs.
static __device__ __forceinline__ void gemm16l(
    float acc[4][4], uint32_t aAddr, uint32_t bAddr, int KT)
{
    #pragma unroll
    for (int ks = 0; ks < KT; ks++) {
        const uint32_t kb = (uint32_t)ks * 32;   // 16 halves = 32 bytes per k-step
        uint32_t a0, a1, a2, a3, p0, p1, p2, p3, q0, q1, q2, q3;
        ldm4(a0, a1, a2, a3, aAddr + kb);
        ldm4(p0, p1, p2, p3, bAddr + kb);
        ldm4(q0, q1, q2, q3, bAddr + 16 * XSTH * 2 + kb);
        mma16(acc[0], a0, a1, a2, a3, p0, p1);
        mma16(acc[1], a0, a1, a2, a3, p2, p3);
        mma16(acc[2], a0, a1, a2, a3, q0, q1);
        mma16(acc[3], a0, a1, a2, a3, q2, q3);
    }
}

// LayerNorm rows r0, r0+step, ... -> fp16 [row][k] stride XSTH.
static __device__ __forceinline__ void ln128s(
    const float* __restrict__ src, long base, int R, __half* dst,
    const float* __restrict__ g, const float* __restrict__ b,
    int r0, int step, int lane)
{
    const int c4 = lane * 4;
    const float4 g4 = *(const float4*)(g + c4);
    const float4 b4 = *(const float4*)(b + c4);
    #pragma unroll
    for (int r = r0; r < P; r += step) {
        long row = base + r;
        float4 x = make_float4(0.f, 0.f, 0.f, 0.f);
        if (row < R) x = *(const float4*)(src + row * (long)CZ + c4);
        float s = x.x + x.y + x.z + x.w;
        float q = fmaf(x.x, x.x, fmaf(x.y, x.y, fmaf(x.z, x.z, x.w * x.w)));
        #pragma unroll
        for (int o = 16; o; o >>= 1) {
            s += __shfl_xor_sync(0xffffffffu, s, o);
            q += __shfl_xor_sync(0xffffffffu, q, o);
        }
        float m  = s * (1.f / CZ);
        float v  = fmaxf(q * (1.f / CZ) - m * m, 0.f);
        float ri = rsqrtf(v + 1e-5f);
        __half* xr = dst + r * XSTH + c4;
        *(__half2*)(xr)     = __floats2half2_rn((x.x - m) * ri * g4.x + b4.x,
                                                (x.y - m) * ri * g4.y + b4.y);
        *(__half2*)(xr + 2) = __floats2half2_rn((x.z - m) * ri * g4.z + b4.z,
                                                (x.w - m) * ri * g4.w + b4.w);
    }
}

// Stage two k-major [128][64] weights into wt[n][k] fp16 (n<64: W1, else W2).
static __device__ __forceinline__ void stageW2(
    __half* wt, const float* __restrict__ W1, const float* __restrict__ W2, int tid)
{
    #pragma unroll 1
    for (int i = tid; i < 4096; i += NT) {
        const int m  = i >> 11;
        const int k  = (i >> 4) & 127;
        const int ng = i & 15;
        const float* Ws = m ? W2 : W1;
        float4 w = *(const float4*)(Ws + k * HD + ng * 4);
        const int n = m * 64 + ng * 4;
        wt[(n + 0) * XSTH + k] = __float2half_rn(w.x);
        wt[(n + 1) * XSTH + k] = __float2half_rn(w.y);
        wt[(n + 2) * XSTH + k] = __float2half_rn(w.z);
        wt[(n + 3) * XSTH + k] = __float2half_rn(w.w);
    }
}

__global__ void __launch_bounds__(NT, 1)
tpa_mma11(const float* __restrict__ tmpl, const float* __restrict__ pair,
          const float* __restrict__ lpg, const float* __restrict__ lpb,
          const float* __restrict__ ltg, const float* __restrict__ ltb,
          const float* __restrict__ Wq,  const float* __restrict__ Wk,
          const float* __restrict__ Wv,  const float* __restrict__ Wg,
          const float* __restrict__ bg,  const float* __restrict__ Wo,
          const float* __restrict__ bo,  float* __restrict__ out,
          int R, int T)
{
    extern __shared__ __align__(16) char smc[];
    __half* xs0 = (__half*)smc;               // 128 x XSTH : LN buffer A
    __half* xs1 = xs0 + P * XSTH;             // 128 x XSTH : LN buffer B
    __half* wt  = xs1 + P * XSTH;             // 128 x XSTH : weights [n][k]
    __half* gs  = wt + P * XSTH;              // 128 x GST  : G gate (fp16)
    float*  rs0 = (float*)(gs + P * GST);     // 512 : rescale parity 0 (p*4+h)
    float*  ws0 = rs0 + 512;                  // 512
    float*  rs1 = ws0 + 512;                  // 512 : parity 1
    float*  ws1 = rs1 + 512;                  // 512
    float*  ls  = ws1 + 512;                  // 512 : 1/l
    float*  bgs = ls + 512;                   // 64
    float*  bos = bgs + HD;                   // 128

    const int tid  = threadIdx.x;
    const int lane = tid & 31;
    const int wid  = tid >> 5;
    const int mt   = wid & 7;         // m-tile (16 rows)
    const int nq   = wid >> 3;        // n quarter (32 cols)
    const int gid  = lane >> 2;
    const int tig  = lane & 3;
    const bool isK = (nq < 2);
    const long base = (long)blockIdx.x * P;

    // ldmatrix lane-address offsets (halves), fixed per thread
    const int lg  = lane >> 3, l7 = lane & 7;
    const uint32_t aOff = (uint32_t)((mt * 16 + (lg & 1) * 8 + l7) * XSTH
                                     + (lg >> 1) * 8) * 2;
    const uint32_t bOff = (uint32_t)((nq * 32 + (lg >> 1) * 8 + l7) * XSTH
                                     + (lg & 1) * 8) * 2;
    const uint32_t xs0A = smem_u32(xs0) + aOff;
    const uint32_t xs1A = smem_u32(xs1) + aOff;
    const uint32_t wtB  = smem_u32(wt) + bOff;

    if (tid < HD)  bgs[tid] = bg[tid];
    else if (tid >= 64 && tid < 64 + CZ) bos[tid - 64] = bo[tid - 64];

    // ---------------- Phase A: LN(pair)->xs0, Wq|Wg, QG GEMM ----------------
    ln128s(pair, base, R, xs0, lpg, lpb, wid, NW, lane);
    stageW2(wt, Wq, Wg, tid);
    __syncthreads();

    float qf[4][4] = {};              // K-warps keep Q; V-warps: temp for G
    gemm16l(qf, xs0A, wtB, 8);
    if (!isK) {                       // sigmoid -> gs (fp16), qf dead afterwards
        const int r0 = mt * 16 + gid, r1 = r0 + 8;
        #pragma unroll
        for (int nt = 0; nt < 4; nt++) {
            const int c = (nq - 2) * 32 + nt * 8 + tig * 2;
            float g0 = 1.f / (1.f + __expf(-(qf[nt][0] + bgs[c])));
            float g1 = 1.f / (1.f + __expf(-(qf[nt][1] + bgs[c + 1])));
            float g2 = 1.f / (1.f + __expf(-(qf[nt][2] + bgs[c])));
            float g3 = 1.f / (1.f + __expf(-(qf[nt][3] + bgs[c + 1])));
            *(__half2*)(gs + r0 * GST + c) = __floats2half2_rn(g0, g1);
            *(__half2*)(gs + r1 * GST + c) = __floats2half2_rn(g2, g3);
        }
    }
    __syncthreads();                  // xs0/wt reads done

    // stage Wk|Wv; LN t0 -> xs0 (warps 0-15), LN t1 -> xs1 (warps 16-31)
    stageW2(wt, Wk, Wv, tid);
    if (wid < 16) ln128s(tmpl, base, R, xs0, ltg, ltb, wid, 16, lane);
    else if (T > 1) ln128s(tmpl + (long)R * CZ, base, R, xs1, ltg, ltb, wid - 16, 16, lane);

    // pv: K-warps -> m4 = pv[0..3], l4 = pv[4..7]; V-warps -> vAcc[nt][j] = pv[nt*4+j]
    float pv[16];
    #pragma unroll
    for (int i = 0; i < 16; i++) pv[i] = 0.f;
    if (isK) {
        #pragma unroll
        for (int i = 0; i < 4; i++) pv[i] = __int_as_float(0xff800000);
    }
    __syncthreads();

    // ---------------- template loop: ONE sync per template ----------------
    #pragma unroll 1
    for (int t = 0; t < T; t++) {
        float* rsb = (t & 1) ? rs1 : rs0;
        float* wsb = (t & 1) ? ws1 : ws0;
        float kv[4][4] = {};
        gemm16l(kv, (t & 1) ? xs1A : xs0A, wtB, 8);

        if (isK) {                    // in-fragment scores + online softmax
            float sc[2][2];           // [rowhalf][headhalf]
            #pragma unroll
            for (int hh = 0; hh < 2; hh++) {
                const int nt0 = hh * 2;
                #pragma unroll
                for (int rh = 0; rh < 2; rh++) {
                    const int j = rh * 2;
                    float s = qf[nt0][j] * kv[nt0][j];
                    s = fmaf(qf[nt0][j + 1],     kv[nt0][j + 1],     s);
                    s = fmaf(qf[nt0 + 1][j],     kv[nt0 + 1][j],     s);
                    s = fmaf(qf[nt0 + 1][j + 1], kv[nt0 + 1][j + 1], s);
                    sc[rh][hh] = s;
                }
            }
            #pragma unroll
            for (int rh = 0; rh < 2; rh++)
                #pragma unroll
                for (int hh = 0; hh < 2; hh++) {
                    float v = sc[rh][hh];
                    v += __shfl_xor_sync(0xffffffffu, v, 1);
                    v += __shfl_xor_sync(0xffffffffu, v, 2);
                    sc[rh][hh] = v;
                }
            if (tig == 0) {
                #pragma unroll
                for (int rh = 0; rh < 2; rh++)
                    #pragma unroll
                    for (int hh = 0; hh < 2; hh++) {
                        const int i = rh * 2 + hh;
                        float sd = sc[rh][hh] * 0.25f;    // 1/sqrt(D=16)
                        float mn = fmaxf(pv[i], sd);
                        float rr = __expf(pv[i] - mn);
                        float ww = __expf(sd - mn);
                        pv[4 + i] = pv[4 + i] * rr + ww;
                        pv[i] = mn;
                        const int r = mt * 16 + rh * 8 + gid;
                        const int h = nq * 2 + hh;
                        rsb[r * 4 + h] = rr;
                        wsb[r * 4 + h] = ww;
                        if (t == T - 1)
                            ls[r * 4 + h] = 1.f / pv[4 + i];
                    }
            }
        }
        __syncthreads();              // rs/ws[t&1] (+ last: ls) ready; xs[t&1] read done

        if (!isK) {                   // V online accumulate into pv
            const int r0 = mt * 16 + gid, r1 = r0 + 8;
            #pragma unroll
            for (int nt = 0; nt < 4; nt++) {
                const int h = (nq - 2) * 2 + (nt >> 1);
                float rr0 = rsb[r0 * 4 + h], ww0 = wsb[r0 * 4 + h];
                float rr1 = rsb[r1 * 4 + h], ww1 = wsb[r1 * 4 + h];
                pv[nt * 4 + 0] = fmaf(pv[nt * 4 + 0], rr0, ww0 * kv[nt][0]);
                pv[nt * 4 + 1] = fmaf(pv[nt * 4 + 1], rr0, ww0 * kv[nt][1]);
                pv[nt * 4 + 2] = fmaf(pv[nt * 4 + 2], rr1, ww1 * kv[nt][2]);
                pv[nt * 4 + 3] = fmaf(pv[nt * 4 + 3], rr1, ww1 * kv[nt][3]);
            }
        }
        if (t + 2 < T)                // prefetch LN(t+2) into just-freed buffer
            ln128s(tmpl + (long)(t + 2) * R * CZ, base, R,
                   (t & 1) ? xs1 : xs0, ltg, ltb, wid, NW, lane);
        if (t == T - 1) {             // stage Wo[k=64][n=128] -> wt[n][k]
            #pragma unroll 1
            for (int i = tid; i < 2048; i += NT) {
                const int k = i >> 5, ng = i & 31;
                float4 w = *(const float4*)(Wo + k * CZ + ng * 4);
                const int n = ng * 4;
                wt[(n + 0) * XSTH + k] = __float2half_rn(w.x);
                wt[(n + 1) * XSTH + k] = __float2half_rn(w.y);
                wt[(n + 2) * XSTH + k] = __float2half_rn(w.z);
                wt[(n + 3) * XSTH + k] = __float2half_rn(w.w);
            }
        }
    }

    // ---------------- Phase C: vals -> xs[T&1], O GEMM ----------------
    __half* xsv = (T & 1) ? xs1 : xs0;    // buffer NOT read by last GEMM
    const uint32_t xsvA = (T & 1) ? xs1A : xs0A;
    if (!isK) {                           // vals = vAcc * G * linv
        const int r0 = mt * 16 + gid, r1 = r0 + 8;
        #pragma unroll
        for (int nt = 0; nt < 4; nt++) {
            const int c = (nq - 2) * 32 + nt * 8 + tig * 2;
            const int h = (nq - 2) * 2 + (nt >> 1);
            float li0 = ls[r0 * 4 + h], li1 = ls[r1 * 4 + h];
            float2 g0 = __half22float2(*(__half2*)(gs + r0 * GST + c));
            float2 g1 = __half22float2(*(__half2*)(gs + r1 * GST + c));
            *(__half2*)(xsv + r0 * XSTH + c) =
                __floats2half2_rn(pv[nt * 4 + 0] * g0.x * li0,
                                  pv[nt * 4 + 1] * g0.y * li0);
            *(__half2*)(xsv + r1 * XSTH + c) =
                __floats2half2_rn(pv[nt * 4 + 2] * g1.x * li1,
                                  pv[nt * 4 + 3] * g1.y * li1);
        }
    }
    __syncthreads();                  // vals + Wo ready

    {
        float oc[4][4] = {};
        gemm16l(oc, xsvA, wtB, 4);
        const long r0 = base + mt * 16 + gid, r1 = r0 + 8;
        #pragma unroll
        for (int nt = 0; nt < 4; nt++) {
            const int c = nq * 32 + nt * 8 + tig * 2;
            if (r0 < R) {
                float2 v = make_float2(oc[nt][0] + bos[c], oc[nt][1] + bos[c + 1]);
                *(float2*)(out + r0 * (long)CZ + c) = v;
            }
            if (r1 < R) {
                float2 v = make_float2(oc[nt][2] + bos[c], oc[nt][3] + bos[c + 1]);
                *(float2*)(out + r1 * (long)CZ + c) = v;
            }
        }
    }
}

extern "C" void kernel_launch(void* const* d_in, const int* in_sizes, int n_in,
                              void* d_out, int out_size)
{
    const float* tmpl = (const float*)d_in[0];
    const float* pair = (const float*)d_in[1];
    const float* lpg  = (const float*)d_in[2];
    const float* lpb  = (const float*)d_in[3];
    const float* ltg  = (const float*)d_in[4];
    const float* ltb  = (const float*)d_in[5];
    const float* Wq   = (const float*)d_in[6];
    const float* Wk   = (const float*)d_in[7];
    const float* Wv   = (const float*)d_in[8];
    const float* Wg   = (const float*)d_in[9];
    const float* bg   = (const float*)d_in[10];
    const float* Wo   = (const float*)d_in[11];
    const float* bo   = (const float*)d_in[12];
    float* out = (float*)d_out;

    const int R = in_sizes[1] / CZ;           // b*n*n pixels
    const int T = in_sizes[0] / in_sizes[1];  // templates

    const size_t smem = (size_t)(3 * P * XSTH + P * GST) * sizeof(__half)
                      + (size_t)(5 * 512 + HD + CZ) * sizeof(float);
    cudaFuncSetAttribute(tpa_mma11, cudaFuncAttributeMaxDynamicSharedMemorySize, (int)smem);

    const int grid = (R + P - 1) / P;
    tpa_mma11<<<grid, NT, smem>>>(tmpl, pair, lpg, lpb, ltg, ltb,
                                  Wq, Wk, Wv, Wg, bg, Wo, bo, out, R, T);
}